// round 3
// baseline (speedup 1.0000x reference)
#include <cuda_runtime.h>
#include <cstdint>
#include <cstddef>

// Problem constants
constexpr int Bb = 2;
constexpr int Nn = 10000;
constexpr int Kk = 20;
constexpr int NP = Bb * Nn;

// Scratch (device globals: no allocations allowed)
__device__ __align__(16) float g_xT[(size_t)NP * 128];   // [b][n][c] layout, C <= 128
__device__ float g_norm[NP];
__device__ int   g_idx[(size_t)NP * Kk];

// ---------------------------------------------------------------------------
// Transpose (B,C,N) -> (B,N,C) slice of a channel-major tensor, plus sq-norms
// xx computed as mul-then-add reduce in ascending c (matches jnp.sum(x*x)).
// ---------------------------------------------------------------------------
__global__ void transpose_norm_kernel(const float* __restrict__ src, int C, int batchStride) {
    int p = blockIdx.x * blockDim.x + threadIdx.x;
    if (p >= NP) return;
    int b = p / Nn, n = p % Nn;
    const float* s = src + (size_t)b * batchStride + n;
    float* d = g_xT + (size_t)p * C;
    float sum = 0.f;
    for (int c = 0; c < C; ++c) {
        float v = s[(size_t)c * Nn];
        d[c] = v;
        sum = __fadd_rn(sum, __fmul_rn(v, v));
    }
    g_norm[p] = sum;
}

// ---------------------------------------------------------------------------
// Brute-force KNN. Replicates reference arithmetic exactly:
//   dot   = ascending-c FMA chain (sequential-k SGEMM accumulator)
//   inner = -2 * dot            (single rounding)
//   pd    = ((-xx_q) - inner) - xx_m   (that exact association)
//   top-k LARGEST pd, tie -> lower index (lax.top_k semantics)
// One thread per query; candidate tile staged in smem.
// ---------------------------------------------------------------------------
template <int C>
__global__ void knn_kernel() {
    constexpr int TM = 16;
    constexpr int TQ = 128;
    __shared__ __align__(16) float ms[TM * C];
    __shared__ float mn[TM];

    int b = blockIdx.y;
    int q = blockIdx.x * TQ + threadIdx.x;
    bool active = q < Nn;
    const float* xb = g_xT + (size_t)b * Nn * C;
    const float* qrow = xb + (size_t)(active ? q : 0) * C;
    float qn = active ? g_norm[b * Nn + q] : 0.f;
    float negqn = -qn;

    float bd[Kk];   // pd values, sorted descending (largest first)
    int bi[Kk];
#pragma unroll
    for (int i = 0; i < Kk; ++i) { bd[i] = -3.4e38f; bi[i] = 0; }

#pragma unroll 1
    for (int mt = 0; mt < Nn; mt += TM) {
        __syncthreads();
        for (int i = threadIdx.x; i < TM * C / 4; i += TQ)
            ((float4*)ms)[i] = ((const float4*)(xb + (size_t)mt * C))[i];
        if (threadIdx.x < TM) mn[threadIdx.x] = g_norm[b * Nn + mt + threadIdx.x];
        __syncthreads();

        float part[TM];
#pragma unroll
        for (int m = 0; m < TM; ++m) part[m] = 0.f;

        constexpr int CH = (C < 16) ? C : 16;
#pragma unroll 1
        for (int cc = 0; cc < C; cc += CH) {
            float qv[CH];
#pragma unroll
            for (int c4 = 0; c4 < CH / 4; ++c4) {
                float4 v = ((const float4*)(qrow + cc))[c4];
                qv[c4 * 4 + 0] = v.x; qv[c4 * 4 + 1] = v.y;
                qv[c4 * 4 + 2] = v.z; qv[c4 * 4 + 3] = v.w;
            }
#pragma unroll
            for (int m = 0; m < TM; ++m) {
#pragma unroll
                for (int c4 = 0; c4 < CH / 4; ++c4) {
                    float4 mv = *((const float4*)&ms[m * C + cc + c4 * 4]);
                    part[m] = __fmaf_rn(qv[c4 * 4 + 0], mv.x, part[m]);
                    part[m] = __fmaf_rn(qv[c4 * 4 + 1], mv.y, part[m]);
                    part[m] = __fmaf_rn(qv[c4 * 4 + 2], mv.z, part[m]);
                    part[m] = __fmaf_rn(qv[c4 * 4 + 3], mv.w, part[m]);
                }
            }
        }

        if (active) {
#pragma unroll
            for (int m = 0; m < TM; ++m) {
                float inner = __fmul_rn(-2.f, part[m]);
                float pdv = __fsub_rn(__fsub_rn(negqn, inner), mn[m]);
                if (pdv > bd[Kk - 1]) {
                    bd[Kk - 1] = pdv; bi[Kk - 1] = mt + m;
#pragma unroll
                    for (int j = Kk - 1; j > 0; --j) {
                        if (bd[j] > bd[j - 1]) {
                            float td = bd[j]; bd[j] = bd[j - 1]; bd[j - 1] = td;
                            int ti = bi[j]; bi[j] = bi[j - 1]; bi[j - 1] = ti;
                        }
                    }
                }
            }
        }
    }

    if (active) {
        int base = (b * Nn + q) * Kk;
#pragma unroll
        for (int k = 0; k < Kk; ++k) g_idx[base + k] = bi[k];
    }
}

// ---------------------------------------------------------------------------
// EdgeConv, bitwise-faithful to the reference GEMM:
//   y_k[o] = FMA chain over c=0..2C-1 of feat_k[c]*w[o][c], feat=[ctr-nb, ctr]
// Phase A accumulates the (ctr-nb)*w1 half per k, Phase B appends ctr*w2
// per k (same operands all k, but rounding depends on running acc_k).
// max over k, then BN (scale>0) + LeakyReLU — transform commutes with max.
// PPB points per block, one thread per output channel.
// ---------------------------------------------------------------------------
template <int CIN, int COUT>
__global__ void edgeconv_kernel(const float* __restrict__ w,
                                const float* __restrict__ gg,
                                const float* __restrict__ bbias,
                                const float* __restrict__ mmean,
                                const float* __restrict__ vvar,
                                float* __restrict__ out, int coff) {
    constexpr int PPB = 4;
    __shared__ __align__(16) float s_dnb[PPB][Kk][CIN];  // ctr - nb (fp32)
    __shared__ __align__(16) float s_ctr[PPB][CIN];
    __shared__ int s_idx[PPB][Kk];

    int p0 = blockIdx.x * PPB;
    int t = threadIdx.x;

    for (int i = t; i < PPB * Kk; i += COUT) {
        int p = i / Kk, k = i % Kk;
        s_idx[p][k] = g_idx[(size_t)(p0 + p) * Kk + k];
    }
    for (int i = t; i < PPB * CIN / 4; i += COUT) {
        int p = i / (CIN / 4), c4 = i % (CIN / 4);
        ((float4*)s_ctr[p])[c4] = ((const float4*)(g_xT + (size_t)(p0 + p) * CIN))[c4];
    }
    __syncthreads();
    for (int i = t; i < PPB * Kk * CIN / 4; i += COUT) {
        int c4 = i % (CIN / 4);
        int rest = i / (CIN / 4);
        int k = rest % Kk, p = rest / Kk;
        int b = (p0 + p) / Nn;
        int m = s_idx[p][k];
        float4 nb = ((const float4*)(g_xT + ((size_t)b * Nn + m) * CIN))[c4];
        float4 ct = ((const float4*)s_ctr[p])[c4];
        float4 dv;
        dv.x = __fsub_rn(ct.x, nb.x); dv.y = __fsub_rn(ct.y, nb.y);
        dv.z = __fsub_rn(ct.z, nb.z); dv.w = __fsub_rn(ct.w, nb.w);
        ((float4*)s_dnb[p][k])[c4] = dv;
    }
    __syncthreads();

    int o = t;
    const float* w1 = w + (size_t)o * 2 * CIN;
    const float* w2 = w1 + CIN;

    float acc[PPB][Kk];
#pragma unroll
    for (int p = 0; p < PPB; ++p)
#pragma unroll
        for (int k = 0; k < Kk; ++k) acc[p][k] = 0.f;

    constexpr int CH = (CIN < 8) ? CIN : 8;

    // Phase A: first C terms of the chain: (ctr - nb_k) * w1
#pragma unroll 1
    for (int cc = 0; cc < CIN; cc += CH) {
        float w1r[CH];
#pragma unroll
        for (int c = 0; c < CH; c += 4) {
            float4 a = *(const float4*)(w1 + cc + c);
            w1r[c + 0] = a.x; w1r[c + 1] = a.y; w1r[c + 2] = a.z; w1r[c + 3] = a.w;
        }
#pragma unroll
        for (int p = 0; p < PPB; ++p)
#pragma unroll
            for (int k = 0; k < Kk; ++k)
#pragma unroll
                for (int c = 0; c < CH; ++c)
                    acc[p][k] = __fmaf_rn(s_dnb[p][k][cc + c], w1r[c], acc[p][k]);
    }

    // Phase B: remaining C terms: ctr * w2, appended per-k (rounding per chain)
#pragma unroll 1
    for (int cc = 0; cc < CIN; cc += CH) {
        float w2r[CH];
#pragma unroll
        for (int c = 0; c < CH; c += 4) {
            float4 a = *(const float4*)(w2 + cc + c);
            w2r[c + 0] = a.x; w2r[c + 1] = a.y; w2r[c + 2] = a.z; w2r[c + 3] = a.w;
        }
#pragma unroll
        for (int p = 0; p < PPB; ++p) {
            float cr[CH];
#pragma unroll
            for (int c = 0; c < CH; ++c) cr[c] = s_ctr[p][cc + c];
#pragma unroll
            for (int k = 0; k < Kk; ++k)
#pragma unroll
                for (int c = 0; c < CH; ++c)
                    acc[p][k] = __fmaf_rn(cr[c], w2r[c], acc[p][k]);
        }
    }

    float scale = __fmul_rn(gg[o], __frsqrt_rn(__fadd_rn(vvar[o], 1e-5f)));
    float shift = __fsub_rn(bbias[o], __fmul_rn(mmean[o], scale));
#pragma unroll
    for (int p = 0; p < PPB; ++p) {
        float mx = acc[p][0];
#pragma unroll
        for (int k = 1; k < Kk; ++k) mx = fmaxf(mx, acc[p][k]);
        float y = __fmaf_rn(mx, scale, shift);
        y = (y >= 0.f) ? y : __fmul_rn(0.2f, y);
        int gp = p0 + p;
        int b = gp / Nn, n = gp % Nn;
        out[((size_t)b * 512 + coff + o) * Nn + n] = y;
    }
}

// ---------------------------------------------------------------------------
extern "C" void kernel_launch(void* const* d_in, const int* in_sizes, int n_in,
                              void* d_out, int out_size) {
    const float* x = (const float*)d_in[0];
    float* out = (float*)d_out;

    const float* w1 = (const float*)d_in[1];
    const float* g1 = (const float*)d_in[2];
    const float* b1 = (const float*)d_in[3];
    const float* m1 = (const float*)d_in[4];
    const float* v1 = (const float*)d_in[5];
    const float* w2 = (const float*)d_in[6];
    const float* g2 = (const float*)d_in[7];
    const float* b2 = (const float*)d_in[8];
    const float* m2 = (const float*)d_in[9];
    const float* v2 = (const float*)d_in[10];
    const float* w3 = (const float*)d_in[11];
    const float* g3 = (const float*)d_in[12];
    const float* b3 = (const float*)d_in[13];
    const float* m3 = (const float*)d_in[14];
    const float* v3 = (const float*)d_in[15];
    const float* w4 = (const float*)d_in[16];
    const float* g4 = (const float*)d_in[17];
    const float* b4 = (const float*)d_in[18];
    const float* m4 = (const float*)d_in[19];
    const float* v4 = (const float*)d_in[20];

    dim3 knn_grid((Nn + 127) / 128, Bb);
    int tp_blocks = (NP + 255) / 256;

    // Layer 1: x (C=4) -> 64 channels at offset 0
    transpose_norm_kernel<<<tp_blocks, 256>>>(x, 4, 4 * Nn);
    knn_kernel<4><<<knn_grid, 128>>>();
    edgeconv_kernel<4, 64><<<NP / 4, 64>>>(w1, g1, b1, m1, v1, out, 0);

    // Layer 2: x1 (C=64) -> 64 channels at offset 64
    transpose_norm_kernel<<<tp_blocks, 256>>>(out + (size_t)0 * Nn, 64, 512 * Nn);
    knn_kernel<64><<<knn_grid, 128>>>();
    edgeconv_kernel<64, 64><<<NP / 4, 64>>>(w2, g2, b2, m2, v2, out, 64);

    // Layer 3: x2 (C=64) -> 128 channels at offset 128
    transpose_norm_kernel<<<tp_blocks, 256>>>(out + (size_t)64 * Nn, 64, 512 * Nn);
    knn_kernel<64><<<knn_grid, 128>>>();
    edgeconv_kernel<64, 128><<<NP / 4, 128>>>(w3, g3, b3, m3, v3, out, 128);

    // Layer 4: x3 (C=128) -> 256 channels at offset 256
    transpose_norm_kernel<<<tp_blocks, 256>>>(out + (size_t)128 * Nn, 128, 512 * Nn);
    knn_kernel<128><<<knn_grid, 128>>>();
    edgeconv_kernel<128, 256><<<NP / 4, 256>>>(w4, g4, b4, m4, v4, out, 256);
}

// round 4
// speedup vs baseline: 1.2232x; 1.2232x over previous
#include <cuda_runtime.h>
#include <cstdint>
#include <cstddef>

// Problem constants
constexpr int Bb = 2;
constexpr int Nn = 10000;
constexpr int Kk = 20;
constexpr int NP = Bb * Nn;
constexpr int SEG = 4;
constexpr int SEGSZ = 2512;   // 2512*3 + 2464 = 10000, all multiples of TM
constexpr int TQ = 128;
constexpr int TM = 16;

// Scratch (device globals: no allocations allowed)
__device__ __align__(16) float g_xT[(size_t)NP * 128];   // [b][n][c], C <= 128
__device__ float g_norm[NP];
__device__ int   g_idx[(size_t)NP * Kk];
__device__ float g_pd[(size_t)NP * SEG * Kk];
__device__ int   g_pi[(size_t)NP * SEG * Kk];

using u64 = unsigned long long;
__device__ __forceinline__ u64 pk2(float lo, float hi) {
    u64 r; asm("mov.b64 %0,{%1,%2};" : "=l"(r) : "f"(lo), "f"(hi)); return r;
}
__device__ __forceinline__ u64 bc2(float v) { return pk2(v, v); }
__device__ __forceinline__ void upk2(u64 v, float& lo, float& hi) {
    asm("mov.b64 {%0,%1},%2;" : "=f"(lo), "=f"(hi) : "l"(v));
}
// Packed fp32 FMA (SASS FFMA2): two independent IEEE fp32 FMAs per instruction.
__device__ __forceinline__ u64 ffma2(u64 a, u64 b, u64 c) {
    u64 d; asm("fma.rn.f32x2 %0,%1,%2,%3;" : "=l"(d) : "l"(a), "l"(b), "l"(c)); return d;
}

// ---------------------------------------------------------------------------
// Transpose (B,C,N) -> (B,N,C) + sq-norms (mul-then-add reduce, ascending c)
// ---------------------------------------------------------------------------
__global__ void transpose_norm_kernel(const float* __restrict__ src, int C, int batchStride) {
    int p = blockIdx.x * blockDim.x + threadIdx.x;
    if (p >= NP) return;
    int b = p / Nn, n = p % Nn;
    const float* s = src + (size_t)b * batchStride + n;
    float* d = g_xT + (size_t)p * C;
    float sum = 0.f;
    for (int c = 0; c < C; ++c) {
        float v = s[(size_t)c * Nn];
        d[c] = v;
        sum = __fadd_rn(sum, __fmul_rn(v, v));
    }
    g_norm[p] = sum;
}

// ---------------------------------------------------------------------------
// KNN partial pass over one candidate segment. Reference arithmetic exactly:
//   dot   = ascending-c FMA chain
//   inner = -2 * dot
//   pd    = ((-xx_q) - inner) - xx_m
// top-k LARGEST pd, tie -> lower index. Candidate pairs packed for FFMA2
// (per-lane chains bitwise identical to scalar version).
// ---------------------------------------------------------------------------
template <int C>
__global__ void knn_part_kernel() {
    __shared__ __align__(16) float ms2[TM * C];   // [pair(8)][c][2]
    __shared__ float mn[TM];

    int b = blockIdx.z, seg = blockIdx.y;
    int q = blockIdx.x * TQ + threadIdx.x;
    bool active = q < Nn;
    const float* xb = g_xT + (size_t)b * Nn * C;
    const float* qrow = xb + (size_t)(active ? q : 0) * C;
    float negqn = active ? -g_norm[b * Nn + q] : 0.f;
    int mt0 = seg * SEGSZ;
    int mt1 = min(Nn, mt0 + SEGSZ);

    float bd[Kk];   // pd values, sorted descending
    int bi[Kk];
#pragma unroll
    for (int i = 0; i < Kk; ++i) { bd[i] = -3.4e38f; bi[i] = 0; }

    auto ins = [&](float pdv, int idx) {
        if (pdv > bd[Kk - 1]) {
            bd[Kk - 1] = pdv; bi[Kk - 1] = idx;
#pragma unroll
            for (int j = Kk - 1; j > 0; --j) {
                if (bd[j] > bd[j - 1]) {
                    float td = bd[j]; bd[j] = bd[j - 1]; bd[j - 1] = td;
                    int ti = bi[j]; bi[j] = bi[j - 1]; bi[j - 1] = ti;
                }
            }
        }
    };

#pragma unroll 1
    for (int mt = mt0; mt < mt1; mt += TM) {
        __syncthreads();
        // stage candidate pairs, interleaved [pair][c][2]
        for (int i = threadIdx.x; i < 8 * (C / 4); i += TQ) {
            int p8 = i / (C / 4), c4 = i % (C / 4);
            float4 a = ((const float4*)(xb + (size_t)(mt + 2 * p8) * C))[c4];
            float4 v = ((const float4*)(xb + (size_t)(mt + 2 * p8 + 1) * C))[c4];
            float* dst = ms2 + p8 * 2 * C + 8 * c4;
            ((float4*)dst)[0] = make_float4(a.x, v.x, a.y, v.y);
            ((float4*)dst)[1] = make_float4(a.z, v.z, a.w, v.w);
        }
        if (threadIdx.x < TM) mn[threadIdx.x] = g_norm[b * Nn + mt + threadIdx.x];
        __syncthreads();

        u64 part2[8];
#pragma unroll
        for (int p = 0; p < 8; ++p) part2[p] = 0ull;  // {0.0f, 0.0f}

        constexpr int CH = (C < 16) ? C : 16;
#pragma unroll 1
        for (int cc = 0; cc < C; cc += CH) {
            u64 qv2[CH];
#pragma unroll
            for (int c4 = 0; c4 < CH / 4; ++c4) {
                float4 v = ((const float4*)(qrow + cc))[c4];
                qv2[c4 * 4 + 0] = bc2(v.x); qv2[c4 * 4 + 1] = bc2(v.y);
                qv2[c4 * 4 + 2] = bc2(v.z); qv2[c4 * 4 + 3] = bc2(v.w);
            }
#pragma unroll
            for (int p = 0; p < 8; ++p) {
                const ulonglong2* src = (const ulonglong2*)(ms2 + p * 2 * C + 2 * cc);
#pragma unroll
                for (int c2 = 0; c2 < CH / 2; ++c2) {
                    ulonglong2 v = src[c2];
                    part2[p] = ffma2(qv2[2 * c2 + 0], v.x, part2[p]);
                    part2[p] = ffma2(qv2[2 * c2 + 1], v.y, part2[p]);
                }
            }
        }

        if (active) {
#pragma unroll
            for (int p = 0; p < 8; ++p) {
                float d0, d1;
                upk2(part2[p], d0, d1);
                {
                    float inner = __fmul_rn(-2.f, d0);
                    float pdv = __fsub_rn(__fsub_rn(negqn, inner), mn[2 * p]);
                    ins(pdv, mt + 2 * p);
                }
                {
                    float inner = __fmul_rn(-2.f, d1);
                    float pdv = __fsub_rn(__fsub_rn(negqn, inner), mn[2 * p + 1]);
                    ins(pdv, mt + 2 * p + 1);
                }
            }
        }
    }

    if (active) {
        size_t base = ((size_t)(b * Nn + q) * SEG + seg) * Kk;
#pragma unroll
        for (int k = 0; k < Kk; ++k) { g_pd[base + k] = bd[k]; g_pi[base + k] = bi[k]; }
    }
}

// ---------------------------------------------------------------------------
// Merge 4 partial top-20 lists per query (ascending segment order preserves
// tie -> lowest index semantics).
// ---------------------------------------------------------------------------
__global__ void knn_merge_kernel() {
    int p = blockIdx.x * blockDim.x + threadIdx.x;
    if (p >= NP) return;
    float bd[Kk]; int bi[Kk];
#pragma unroll
    for (int i = 0; i < Kk; ++i) { bd[i] = -3.4e38f; bi[i] = 0; }
    size_t base = (size_t)p * SEG * Kk;
#pragma unroll 1
    for (int e = 0; e < SEG * Kk; ++e) {
        float pdv = g_pd[base + e];
        int idx = g_pi[base + e];
        if (pdv > bd[Kk - 1]) {
            bd[Kk - 1] = pdv; bi[Kk - 1] = idx;
#pragma unroll
            for (int j = Kk - 1; j > 0; --j) {
                if (bd[j] > bd[j - 1]) {
                    float td = bd[j]; bd[j] = bd[j - 1]; bd[j - 1] = td;
                    int ti = bi[j]; bi[j] = bi[j - 1]; bi[j - 1] = ti;
                }
            }
        }
    }
#pragma unroll
    for (int k = 0; k < Kk; ++k) g_idx[(size_t)p * Kk + k] = bi[k];
}

// ---------------------------------------------------------------------------
// EdgeConv, bitwise-faithful FMA chain per (point, k, out-channel):
//   y_k[o] = sum_{c<2C} feat_k[c]*w[o][c], feat=[ctr-nb, ctr], sequential c.
// k's packed in pairs for FFMA2. THREADS = COUT*PG; each thread handles
// PT=4 points; PPB = 4*PG points per block.
// ---------------------------------------------------------------------------
template <int CIN, int COUT, int PG>
__global__ void edgeconv_kernel(const float* __restrict__ w,
                                const float* __restrict__ gg,
                                const float* __restrict__ bbias,
                                const float* __restrict__ mmean,
                                const float* __restrict__ vvar,
                                float* __restrict__ out, int coff) {
    constexpr int PT = 4;
    constexpr int PPB = PT * PG;
    constexpr int THREADS = COUT * PG;
    constexpr int K2 = Kk / 2;

    __shared__ __align__(16) float s_dnb2[PPB * K2 * CIN * 2];  // [p][j][c][2]
    __shared__ __align__(16) float s_ctr[PPB][CIN];
    __shared__ int s_idx[PPB][Kk];

    int p0 = blockIdx.x * PPB;
    int t = threadIdx.x;

    for (int i = t; i < PPB * Kk; i += THREADS) {
        int p = i / Kk, k = i % Kk;
        s_idx[p][k] = g_idx[(size_t)(p0 + p) * Kk + k];
    }
    for (int i = t; i < PPB * CIN / 4; i += THREADS) {
        int p = i / (CIN / 4), c4 = i % (CIN / 4);
        ((float4*)s_ctr[p])[c4] = ((const float4*)(g_xT + (size_t)(p0 + p) * CIN))[c4];
    }
    __syncthreads();
    for (int i = t; i < PPB * K2 * (CIN / 4); i += THREADS) {
        int c4 = i % (CIN / 4);
        int rest = i / (CIN / 4);
        int j = rest % K2, p = rest / K2;
        int bo = (p0 + p) / Nn;
        int i0 = s_idx[p][2 * j], i1 = s_idx[p][2 * j + 1];
        float4 n0 = ((const float4*)(g_xT + ((size_t)bo * Nn + i0) * CIN))[c4];
        float4 n1 = ((const float4*)(g_xT + ((size_t)bo * Nn + i1) * CIN))[c4];
        float4 ct = ((const float4*)s_ctr[p])[c4];
        float* dst = s_dnb2 + ((size_t)(p * K2 + j) * CIN) * 2 + 8 * c4;
        ((float4*)dst)[0] = make_float4(__fsub_rn(ct.x, n0.x), __fsub_rn(ct.x, n1.x),
                                        __fsub_rn(ct.y, n0.y), __fsub_rn(ct.y, n1.y));
        ((float4*)dst)[1] = make_float4(__fsub_rn(ct.z, n0.z), __fsub_rn(ct.z, n1.z),
                                        __fsub_rn(ct.w, n0.w), __fsub_rn(ct.w, n1.w));
    }
    __syncthreads();

    int o = t % COUT;
    int pbase = (t / COUT) * PT;
    const float* w1 = w + (size_t)o * 2 * CIN;
    const float* w2 = w1 + CIN;

    u64 acc2[PT][K2];
#pragma unroll
    for (int pt = 0; pt < PT; ++pt)
#pragma unroll
        for (int j = 0; j < K2; ++j) acc2[pt][j] = 0ull;

    constexpr int CH = (CIN < 8) ? CIN : 8;

    // Phase A: (ctr - nb_k) * w1, per-k FMA chain (packed across k-pairs)
#pragma unroll 1
    for (int cc = 0; cc < CIN; cc += CH) {
        u64 w1p[CH];
#pragma unroll
        for (int c4 = 0; c4 < CH / 4; ++c4) {
            float4 a = *(const float4*)(w1 + cc + c4 * 4);
            w1p[c4 * 4 + 0] = bc2(a.x); w1p[c4 * 4 + 1] = bc2(a.y);
            w1p[c4 * 4 + 2] = bc2(a.z); w1p[c4 * 4 + 3] = bc2(a.w);
        }
#pragma unroll
        for (int pt = 0; pt < PT; ++pt) {
            int p = pbase + pt;
#pragma unroll
            for (int j = 0; j < K2; ++j) {
                const ulonglong2* src =
                    (const ulonglong2*)(s_dnb2 + ((size_t)(p * K2 + j) * CIN + cc) * 2);
#pragma unroll
                for (int c2 = 0; c2 < CH / 2; ++c2) {
                    ulonglong2 v = src[c2];
                    acc2[pt][j] = ffma2(v.x, w1p[2 * c2 + 0], acc2[pt][j]);
                    acc2[pt][j] = ffma2(v.y, w1p[2 * c2 + 1], acc2[pt][j]);
                }
            }
        }
    }

    // Phase B: ctr * w2 appended per-k (per-chain rounding)
#pragma unroll 1
    for (int cc = 0; cc < CIN; cc += CH) {
        u64 w2p[CH];
#pragma unroll
        for (int c4 = 0; c4 < CH / 4; ++c4) {
            float4 a = *(const float4*)(w2 + cc + c4 * 4);
            w2p[c4 * 4 + 0] = bc2(a.x); w2p[c4 * 4 + 1] = bc2(a.y);
            w2p[c4 * 4 + 2] = bc2(a.z); w2p[c4 * 4 + 3] = bc2(a.w);
        }
#pragma unroll
        for (int pt = 0; pt < PT; ++pt) {
            int p = pbase + pt;
            u64 cp[CH];
#pragma unroll
            for (int c = 0; c < CH; ++c) cp[c] = bc2(s_ctr[p][cc + c]);
#pragma unroll
            for (int j = 0; j < K2; ++j)
#pragma unroll
                for (int c = 0; c < CH; ++c)
                    acc2[pt][j] = ffma2(cp[c], w2p[c], acc2[pt][j]);
        }
    }

    float scale = __fmul_rn(gg[o], __frsqrt_rn(__fadd_rn(vvar[o], 1e-5f)));
    float shift = __fsub_rn(bbias[o], __fmul_rn(mmean[o], scale));
#pragma unroll
    for (int pt = 0; pt < PT; ++pt) {
        float mx = -3.4e38f;
#pragma unroll
        for (int j = 0; j < K2; ++j) {
            float a, b2;
            upk2(acc2[pt][j], a, b2);
            mx = fmaxf(mx, fmaxf(a, b2));
        }
        float y = __fmaf_rn(mx, scale, shift);
        y = (y >= 0.f) ? y : __fmul_rn(0.2f, y);
        int gp = p0 + pbase + pt;
        int b = gp / Nn, n = gp % Nn;
        out[((size_t)b * 512 + coff + o) * Nn + n] = y;
    }
}

// ---------------------------------------------------------------------------
extern "C" void kernel_launch(void* const* d_in, const int* in_sizes, int n_in,
                              void* d_out, int out_size) {
    const float* x = (const float*)d_in[0];
    float* out = (float*)d_out;

    const float* w1 = (const float*)d_in[1];
    const float* g1 = (const float*)d_in[2];
    const float* b1 = (const float*)d_in[3];
    const float* m1 = (const float*)d_in[4];
    const float* v1 = (const float*)d_in[5];
    const float* w2 = (const float*)d_in[6];
    const float* g2 = (const float*)d_in[7];
    const float* b2 = (const float*)d_in[8];
    const float* m2 = (const float*)d_in[9];
    const float* v2 = (const float*)d_in[10];
    const float* w3 = (const float*)d_in[11];
    const float* g3 = (const float*)d_in[12];
    const float* b3 = (const float*)d_in[13];
    const float* m3 = (const float*)d_in[14];
    const float* v3 = (const float*)d_in[15];
    const float* w4 = (const float*)d_in[16];
    const float* g4 = (const float*)d_in[17];
    const float* b4 = (const float*)d_in[18];
    const float* m4 = (const float*)d_in[19];
    const float* v4 = (const float*)d_in[20];

    dim3 knn_grid((Nn + TQ - 1) / TQ, SEG, Bb);
    int tp_blocks = (NP + 255) / 256;
    int mg_blocks = (NP + 127) / 128;

    // Layer 1: x (C=4) -> 64 channels at offset 0
    transpose_norm_kernel<<<tp_blocks, 256>>>(x, 4, 4 * Nn);
    knn_part_kernel<4><<<knn_grid, TQ>>>();
    knn_merge_kernel<<<mg_blocks, 128>>>();
    edgeconv_kernel<4, 64, 2><<<NP / 8, 128>>>(w1, g1, b1, m1, v1, out, 0);

    // Layer 2: x1 (C=64) -> 64 channels at offset 64
    transpose_norm_kernel<<<tp_blocks, 256>>>(out + (size_t)0 * Nn, 64, 512 * Nn);
    knn_part_kernel<64><<<knn_grid, TQ>>>();
    knn_merge_kernel<<<mg_blocks, 128>>>();
    edgeconv_kernel<64, 64, 2><<<NP / 8, 128>>>(w2, g2, b2, m2, v2, out, 64);

    // Layer 3: x2 (C=64) -> 128 channels at offset 128
    transpose_norm_kernel<<<tp_blocks, 256>>>(out + (size_t)64 * Nn, 64, 512 * Nn);
    knn_part_kernel<64><<<knn_grid, TQ>>>();
    knn_merge_kernel<<<mg_blocks, 128>>>();
    edgeconv_kernel<64, 128, 1><<<NP / 4, 128>>>(w3, g3, b3, m3, v3, out, 128);

    // Layer 4: x3 (C=128) -> 256 channels at offset 256
    transpose_norm_kernel<<<tp_blocks, 256>>>(out + (size_t)128 * Nn, 128, 512 * Nn);
    knn_part_kernel<128><<<knn_grid, TQ>>>();
    knn_merge_kernel<<<mg_blocks, 128>>>();
    edgeconv_kernel<128, 256, 1><<<NP / 4, 256>>>(w4, g4, b4, m4, v4, out, 256);
}

// round 5
// speedup vs baseline: 1.2771x; 1.0441x over previous
#include <cuda_runtime.h>
#include <cstdint>
#include <cstddef>

// Problem constants
constexpr int Bb = 2;
constexpr int Nn = 10000;
constexpr int Kk = 20;
constexpr int NP = Bb * Nn;
constexpr int SEG = 8;
constexpr int SEGSZ = 1264;   // 79*16; 7*1264 + 1152 = 10000, all multiples of TM
constexpr int TQ = 128;
constexpr int TM = 16;
constexpr int QT = 2;         // queries per thread
constexpr int QB = TQ * QT;   // queries per block

// Scratch (device globals: no allocations allowed)
__device__ __align__(16) float g_xT[(size_t)NP * 128];   // [b][n][c], C <= 128
__device__ float g_norm[NP];
__device__ int   g_idx[(size_t)NP * Kk];
__device__ float g_pd[(size_t)NP * SEG * Kk];
__device__ int   g_pi[(size_t)NP * SEG * Kk];

using u64 = unsigned long long;
__device__ __forceinline__ u64 pk2(float lo, float hi) {
    u64 r; asm("mov.b64 %0,{%1,%2};" : "=l"(r) : "f"(lo), "f"(hi)); return r;
}
__device__ __forceinline__ u64 bc2(float v) { return pk2(v, v); }
__device__ __forceinline__ void upk2(u64 v, float& lo, float& hi) {
    asm("mov.b64 {%0,%1},%2;" : "=f"(lo), "=f"(hi) : "l"(v));
}
// Packed fp32 FMA (SASS FFMA2): two independent IEEE fp32 FMAs per instruction.
__device__ __forceinline__ u64 ffma2(u64 a, u64 b, u64 c) {
    u64 d; asm("fma.rn.f32x2 %0,%1,%2,%3;" : "=l"(d) : "l"(a), "l"(b), "l"(c)); return d;
}

// ---------------------------------------------------------------------------
// Transpose (B,C,N) -> (B,N,C) + sq-norms (mul-then-add reduce, ascending c)
// ---------------------------------------------------------------------------
__global__ void transpose_norm_kernel(const float* __restrict__ src, int C, int batchStride) {
    int p = blockIdx.x * blockDim.x + threadIdx.x;
    if (p >= NP) return;
    int b = p / Nn, n = p % Nn;
    const float* s = src + (size_t)b * batchStride + n;
    float* d = g_xT + (size_t)p * C;
    float sum = 0.f;
    for (int c = 0; c < C; ++c) {
        float v = s[(size_t)c * Nn];
        d[c] = v;
        sum = __fadd_rn(sum, __fmul_rn(v, v));
    }
    g_norm[p] = sum;
}

// ---------------------------------------------------------------------------
// KNN partial pass over one candidate segment. Reference arithmetic exactly:
//   dot   = ascending-c FMA chain;  inner = -2*dot;  pd = ((-xxq)-inner)-xxm
// top-k LARGEST pd, tie -> lower index. QT=2 queries/thread; top-k lists in
// smem (threshold cached in a register); candidate pairs packed for FFMA2.
// ---------------------------------------------------------------------------
template <int C>
__global__ void __launch_bounds__(TQ) knn_part_kernel() {
    __shared__ __align__(16) float ms2[TM * C];          // [pair(8)][c][2]
    __shared__ float mn[TM];
    __shared__ float s_bd[QT][Kk][TQ];
    __shared__ unsigned short s_bi[QT][Kk][TQ];

    int b = blockIdx.z, seg = blockIdx.y;
    int t = threadIdx.x;
    int qb = blockIdx.x * QB;
    const float* xb = g_xT + (size_t)b * Nn * C;

    int q[QT]; bool act[QT]; const float* qrow[QT]; float negqn[QT];
#pragma unroll
    for (int s = 0; s < QT; ++s) {
        q[s] = qb + s * TQ + t;
        act[s] = q[s] < Nn;
        qrow[s] = xb + (size_t)(act[s] ? q[s] : 0) * C;
        negqn[s] = act[s] ? -g_norm[b * Nn + q[s]] : 0.f;
    }

#pragma unroll
    for (int s = 0; s < QT; ++s)
#pragma unroll
        for (int k = 0; k < Kk; ++k) { s_bd[s][k][t] = -3.4e38f; s_bi[s][k][t] = 0; }
    float thresh[QT] = {-3.4e38f, -3.4e38f};

    int mt0 = seg * SEGSZ;
    int mt1 = min(Nn, mt0 + SEGSZ);

#pragma unroll 1
    for (int mt = mt0; mt < mt1; mt += TM) {
        __syncthreads();
        for (int i = t; i < 8 * (C / 4); i += TQ) {
            int p8 = i / (C / 4), c4 = i % (C / 4);
            float4 a = ((const float4*)(xb + (size_t)(mt + 2 * p8) * C))[c4];
            float4 v = ((const float4*)(xb + (size_t)(mt + 2 * p8 + 1) * C))[c4];
            float* dst = ms2 + p8 * 2 * C + 8 * c4;
            ((float4*)dst)[0] = make_float4(a.x, v.x, a.y, v.y);
            ((float4*)dst)[1] = make_float4(a.z, v.z, a.w, v.w);
        }
        if (t < TM) mn[t] = g_norm[b * Nn + mt + t];
        __syncthreads();

        u64 part2[QT][8];
#pragma unroll
        for (int s = 0; s < QT; ++s)
#pragma unroll
            for (int p = 0; p < 8; ++p) part2[s][p] = 0ull;

        constexpr int CH = (C < 8) ? C : 8;
#pragma unroll 1
        for (int cc = 0; cc < C; cc += CH) {
            u64 qv2[QT][CH];
#pragma unroll
            for (int s = 0; s < QT; ++s)
#pragma unroll
                for (int c4 = 0; c4 < CH / 4; ++c4) {
                    float4 v = ((const float4*)(qrow[s] + cc))[c4];
                    qv2[s][c4 * 4 + 0] = bc2(v.x); qv2[s][c4 * 4 + 1] = bc2(v.y);
                    qv2[s][c4 * 4 + 2] = bc2(v.z); qv2[s][c4 * 4 + 3] = bc2(v.w);
                }
#pragma unroll
            for (int p = 0; p < 8; ++p) {
                const ulonglong2* src = (const ulonglong2*)(ms2 + p * 2 * C + 2 * cc);
#pragma unroll
                for (int c2 = 0; c2 < CH / 2; ++c2) {
                    ulonglong2 v = src[c2];
#pragma unroll
                    for (int s = 0; s < QT; ++s) {
                        part2[s][p] = ffma2(qv2[s][2 * c2 + 0], v.x, part2[s][p]);
                        part2[s][p] = ffma2(qv2[s][2 * c2 + 1], v.y, part2[s][p]);
                    }
                }
            }
        }

#pragma unroll
        for (int p = 0; p < 8; ++p) {
#pragma unroll
            for (int s = 0; s < QT; ++s) {
                if (!act[s]) continue;
                float d0, d1;
                upk2(part2[s][p], d0, d1);
#pragma unroll
                for (int h = 0; h < 2; ++h) {
                    float dd = h ? d1 : d0;
                    float inner = __fmul_rn(-2.f, dd);
                    float pdv = __fsub_rn(__fsub_rn(negqn[s], inner), mn[2 * p + h]);
                    if (pdv > thresh[s]) {
                        int idx = mt + 2 * p + h;
                        int j = Kk - 1;
#pragma unroll 1
                        while (j > 0) {
                            float prev = s_bd[s][j - 1][t];
                            if (pdv > prev) {
                                s_bd[s][j][t] = prev;
                                s_bi[s][j][t] = s_bi[s][j - 1][t];
                                --j;
                            } else break;
                        }
                        s_bd[s][j][t] = pdv;
                        s_bi[s][j][t] = (unsigned short)idx;
                        thresh[s] = s_bd[s][Kk - 1][t];
                    }
                }
            }
        }
    }

#pragma unroll
    for (int s = 0; s < QT; ++s) {
        if (!act[s]) continue;
        size_t base = ((size_t)(b * Nn + q[s]) * SEG + seg) * Kk;
#pragma unroll
        for (int k = 0; k < Kk; ++k) {
            g_pd[base + k] = s_bd[s][k][t];
            g_pi[base + k] = (int)s_bi[s][k][t];
        }
    }
}

// ---------------------------------------------------------------------------
// Merge SEG partial top-20 lists per query (ascending segment order preserves
// tie -> lowest index semantics).
// ---------------------------------------------------------------------------
__global__ void knn_merge_kernel() {
    int p = blockIdx.x * blockDim.x + threadIdx.x;
    if (p >= NP) return;
    float bd[Kk]; int bi[Kk];
#pragma unroll
    for (int i = 0; i < Kk; ++i) { bd[i] = -3.4e38f; bi[i] = 0; }
    size_t base = (size_t)p * SEG * Kk;
#pragma unroll 1
    for (int e = 0; e < SEG * Kk; ++e) {
        float pdv = g_pd[base + e];
        int idx = g_pi[base + e];
        if (pdv > bd[Kk - 1]) {
            bd[Kk - 1] = pdv; bi[Kk - 1] = idx;
#pragma unroll
            for (int j = Kk - 1; j > 0; --j) {
                if (bd[j] > bd[j - 1]) {
                    float td = bd[j]; bd[j] = bd[j - 1]; bd[j - 1] = td;
                    int ti = bi[j]; bi[j] = bi[j - 1]; bi[j - 1] = ti;
                }
            }
        }
    }
#pragma unroll
    for (int k = 0; k < Kk; ++k) g_idx[(size_t)p * Kk + k] = bi[k];
}

// ---------------------------------------------------------------------------
// EdgeConv, bitwise-faithful FMA chain per (point, k, out-channel):
//   y_k[o] = sum_{c<2C} feat_k[c]*w[o][c], feat=[ctr-nb, ctr], sequential c.
// k's packed in pairs for FFMA2. THREADS = COUT*PG; each thread handles
// PT=4 points; PPB = 4*PG points per block.
// ---------------------------------------------------------------------------
template <int CIN, int COUT, int PG>
__global__ void edgeconv_kernel(const float* __restrict__ w,
                                const float* __restrict__ gg,
                                const float* __restrict__ bbias,
                                const float* __restrict__ mmean,
                                const float* __restrict__ vvar,
                                float* __restrict__ out, int coff) {
    constexpr int PT = 4;
    constexpr int PPB = PT * PG;
    constexpr int THREADS = COUT * PG;
    constexpr int K2 = Kk / 2;

    __shared__ __align__(16) float s_dnb2[PPB * K2 * CIN * 2];  // [p][j][c][2]
    __shared__ __align__(16) float s_ctr[PPB][CIN];
    __shared__ int s_idx[PPB][Kk];

    int p0 = blockIdx.x * PPB;
    int t = threadIdx.x;

    for (int i = t; i < PPB * Kk; i += THREADS) {
        int p = i / Kk, k = i % Kk;
        s_idx[p][k] = g_idx[(size_t)(p0 + p) * Kk + k];
    }
    for (int i = t; i < PPB * CIN / 4; i += THREADS) {
        int p = i / (CIN / 4), c4 = i % (CIN / 4);
        ((float4*)s_ctr[p])[c4] = ((const float4*)(g_xT + (size_t)(p0 + p) * CIN))[c4];
    }
    __syncthreads();
    for (int i = t; i < PPB * K2 * (CIN / 4); i += THREADS) {
        int c4 = i % (CIN / 4);
        int rest = i / (CIN / 4);
        int j = rest % K2, p = rest / K2;
        int bo = (p0 + p) / Nn;
        int i0 = s_idx[p][2 * j], i1 = s_idx[p][2 * j + 1];
        float4 n0 = ((const float4*)(g_xT + ((size_t)bo * Nn + i0) * CIN))[c4];
        float4 n1 = ((const float4*)(g_xT + ((size_t)bo * Nn + i1) * CIN))[c4];
        float4 ct = ((const float4*)s_ctr[p])[c4];
        float* dst = s_dnb2 + ((size_t)(p * K2 + j) * CIN) * 2 + 8 * c4;
        ((float4*)dst)[0] = make_float4(__fsub_rn(ct.x, n0.x), __fsub_rn(ct.x, n1.x),
                                        __fsub_rn(ct.y, n0.y), __fsub_rn(ct.y, n1.y));
        ((float4*)dst)[1] = make_float4(__fsub_rn(ct.z, n0.z), __fsub_rn(ct.z, n1.z),
                                        __fsub_rn(ct.w, n0.w), __fsub_rn(ct.w, n1.w));
    }
    __syncthreads();

    int o = t % COUT;
    int pbase = (t / COUT) * PT;
    const float* w1 = w + (size_t)o * 2 * CIN;
    const float* w2 = w1 + CIN;

    u64 acc2[PT][K2];
#pragma unroll
    for (int pt = 0; pt < PT; ++pt)
#pragma unroll
        for (int j = 0; j < K2; ++j) acc2[pt][j] = 0ull;

    constexpr int CH = (CIN < 8) ? CIN : 8;

    // Phase A: (ctr - nb_k) * w1, per-k FMA chain (packed across k-pairs)
#pragma unroll 1
    for (int cc = 0; cc < CIN; cc += CH) {
        u64 w1p[CH];
#pragma unroll
        for (int c4 = 0; c4 < CH / 4; ++c4) {
            float4 a = *(const float4*)(w1 + cc + c4 * 4);
            w1p[c4 * 4 + 0] = bc2(a.x); w1p[c4 * 4 + 1] = bc2(a.y);
            w1p[c4 * 4 + 2] = bc2(a.z); w1p[c4 * 4 + 3] = bc2(a.w);
        }
#pragma unroll
        for (int pt = 0; pt < PT; ++pt) {
            int p = pbase + pt;
#pragma unroll
            for (int j = 0; j < K2; ++j) {
                const ulonglong2* src =
                    (const ulonglong2*)(s_dnb2 + ((size_t)(p * K2 + j) * CIN + cc) * 2);
#pragma unroll
                for (int c2 = 0; c2 < CH / 2; ++c2) {
                    ulonglong2 v = src[c2];
                    acc2[pt][j] = ffma2(v.x, w1p[2 * c2 + 0], acc2[pt][j]);
                    acc2[pt][j] = ffma2(v.y, w1p[2 * c2 + 1], acc2[pt][j]);
                }
            }
        }
    }

    // Phase B: ctr * w2 appended per-k (per-chain rounding)
#pragma unroll 1
    for (int cc = 0; cc < CIN; cc += CH) {
        u64 w2p[CH];
#pragma unroll
        for (int c4 = 0; c4 < CH / 4; ++c4) {
            float4 a = *(const float4*)(w2 + cc + c4 * 4);
            w2p[c4 * 4 + 0] = bc2(a.x); w2p[c4 * 4 + 1] = bc2(a.y);
            w2p[c4 * 4 + 2] = bc2(a.z); w2p[c4 * 4 + 3] = bc2(a.w);
        }
#pragma unroll
        for (int pt = 0; pt < PT; ++pt) {
            int p = pbase + pt;
            u64 cp[CH];
#pragma unroll
            for (int c = 0; c < CH; ++c) cp[c] = bc2(s_ctr[p][cc + c]);
#pragma unroll
            for (int j = 0; j < K2; ++j)
#pragma unroll
                for (int c = 0; c < CH; ++c)
                    acc2[pt][j] = ffma2(cp[c], w2p[c], acc2[pt][j]);
        }
    }

    float scale = __fmul_rn(gg[o], __frsqrt_rn(__fadd_rn(vvar[o], 1e-5f)));
    float shift = __fsub_rn(bbias[o], __fmul_rn(mmean[o], scale));
#pragma unroll
    for (int pt = 0; pt < PT; ++pt) {
        float mx = -3.4e38f;
#pragma unroll
        for (int j = 0; j < K2; ++j) {
            float a, b2;
            upk2(acc2[pt][j], a, b2);
            mx = fmaxf(mx, fmaxf(a, b2));
        }
        float y = __fmaf_rn(mx, scale, shift);
        y = (y >= 0.f) ? y : __fmul_rn(0.2f, y);
        int gp = p0 + pbase + pt;
        int b = gp / Nn, n = gp % Nn;
        out[((size_t)b * 512 + coff + o) * Nn + n] = y;
    }
}

// ---------------------------------------------------------------------------
extern "C" void kernel_launch(void* const* d_in, const int* in_sizes, int n_in,
                              void* d_out, int out_size) {
    const float* x = (const float*)d_in[0];
    float* out = (float*)d_out;

    const float* w1 = (const float*)d_in[1];
    const float* g1 = (const float*)d_in[2];
    const float* b1 = (const float*)d_in[3];
    const float* m1 = (const float*)d_in[4];
    const float* v1 = (const float*)d_in[5];
    const float* w2 = (const float*)d_in[6];
    const float* g2 = (const float*)d_in[7];
    const float* b2 = (const float*)d_in[8];
    const float* m2 = (const float*)d_in[9];
    const float* v2 = (const float*)d_in[10];
    const float* w3 = (const float*)d_in[11];
    const float* g3 = (const float*)d_in[12];
    const float* b3 = (const float*)d_in[13];
    const float* m3 = (const float*)d_in[14];
    const float* v3 = (const float*)d_in[15];
    const float* w4 = (const float*)d_in[16];
    const float* g4 = (const float*)d_in[17];
    const float* b4 = (const float*)d_in[18];
    const float* m4 = (const float*)d_in[19];
    const float* v4 = (const float*)d_in[20];

    dim3 knn_grid((Nn + QB - 1) / QB, SEG, Bb);
    int tp_blocks = (NP + 255) / 256;
    int mg_blocks = (NP + 127) / 128;

    // Layer 1: x (C=4) -> 64 channels at offset 0
    transpose_norm_kernel<<<tp_blocks, 256>>>(x, 4, 4 * Nn);
    knn_part_kernel<4><<<knn_grid, TQ>>>();
    knn_merge_kernel<<<mg_blocks, 128>>>();
    edgeconv_kernel<4, 64, 2><<<NP / 8, 128>>>(w1, g1, b1, m1, v1, out, 0);

    // Layer 2: x1 (C=64) -> 64 channels at offset 64
    transpose_norm_kernel<<<tp_blocks, 256>>>(out + (size_t)0 * Nn, 64, 512 * Nn);
    knn_part_kernel<64><<<knn_grid, TQ>>>();
    knn_merge_kernel<<<mg_blocks, 128>>>();
    edgeconv_kernel<64, 64, 2><<<NP / 8, 128>>>(w2, g2, b2, m2, v2, out, 64);

    // Layer 3: x2 (C=64) -> 128 channels at offset 128
    transpose_norm_kernel<<<tp_blocks, 256>>>(out + (size_t)64 * Nn, 64, 512 * Nn);
    knn_part_kernel<64><<<knn_grid, TQ>>>();
    knn_merge_kernel<<<mg_blocks, 128>>>();
    edgeconv_kernel<64, 128, 1><<<NP / 4, 128>>>(w3, g3, b3, m3, v3, out, 128);

    // Layer 4: x3 (C=128) -> 256 channels at offset 256
    transpose_norm_kernel<<<tp_blocks, 256>>>(out + (size_t)128 * Nn, 128, 512 * Nn);
    knn_part_kernel<128><<<knn_grid, TQ>>>();
    knn_merge_kernel<<<mg_blocks, 128>>>();
    edgeconv_kernel<128, 256, 1><<<NP / 4, 256>>>(w4, g4, b4, m4, v4, out, 256);
}